// round 2
// baseline (speedup 1.0000x reference)
#include <cuda_runtime.h>
#include <cstdint>

#define NIMG   16
#define NBOX   25200
#define NCH    85
#define NC     80
#define NBINS  4096
#define CAP    4096
#define TOPK_N 1000
#define MAXDET 300
#define CONF   0.25f
#define IOU_T  0.45f
#define MAXWH  4096.0f
#define TILE   48                  // boxes per block tile (25200 = 525*48)

// ---------------- scratch (static device memory; no allocations) ----------------
__device__ int                g_hist[NIMG][NBINS];
__device__ int                g_cnt[NIMG];
__device__ int                g_T[NIMG];
__device__ unsigned long long g_cand[NIMG][CAP];
__device__ float4             g_selbox[NIMG][TOPK_N];
__device__ float4             g_offbox[NIMG][TOPK_N];
__device__ float              g_score[NIMG][TOPK_N];
__device__ float              g_cls[NIMG][TOPK_N];
__device__ unsigned           g_mask[NIMG][TOPK_N][32];

// ---------------- kernel 0: zero scratch + output ----------------
__global__ void k_zero(float* __restrict__ out) {
    int i = blockIdx.x * blockDim.x + threadIdx.x;
    if (i < NIMG * NBINS) ((int*)g_hist)[i] = 0;
    if (i < NIMG)         g_cnt[i] = 0;
    if (i < NIMG * MAXDET * 6) out[i] = 0.0f;
}

// ---------------- kernel 1: score histogram (smem-staged, coalesced) ----------------
// bin = (float_bits >> 12) - 0x3E800 : monotone map of score in (0.25, 1.0) -> [0, 4095]
__global__ void k_hist(const float* __restrict__ x) {
    __shared__ float tl[TILE * NCH];     // 16320 B
    __shared__ int   sh[NBINS];          // 16384 B
    int b = blockIdx.y;
    for (int i = threadIdx.x; i < NBINS; i += blockDim.x) sh[i] = 0;

    // coalesced float4 tile load: base offset is a multiple of 4 floats (16 B)
    size_t base = ((size_t)b * NBOX + (size_t)blockIdx.x * TILE) * NCH;
    const float4* src = (const float4*)(x + base);
    float4* dst = (float4*)tl;
    #pragma unroll
    for (int i = threadIdx.x; i < TILE * NCH / 4; i += 256) dst[i] = src[i];
    __syncthreads();

    for (int it = threadIdx.x; it < TILE * NC; it += 256) {
        int box = it / NC;
        int c = it - box * NC;
        float obj = tl[box * NCH + 4];
        float s = __fmul_rn(tl[box * NCH + 5 + c], obj);
        if (obj > CONF && s > CONF) {
            int bin = (int)(__float_as_uint(s) >> 12) - 0x3E800;
            bin = min(max(bin, 0), NBINS - 1);
            atomicAdd(&sh[bin], 1);
        }
    }
    __syncthreads();
    for (int i = threadIdx.x; i < NBINS; i += blockDim.x)
        if (sh[i]) atomicAdd(&g_hist[b][i], sh[i]);
}

// ---------------- kernel 2: per-image suffix scan -> threshold bin ----------------
__global__ void k_thresh() {
    int b = blockIdx.x;
    __shared__ int s[NBINS];
    const int T = 512;                 // blockDim.x
    for (int i = threadIdx.x; i < NBINS; i += T) s[i] = g_hist[b][i];
    __syncthreads();
    // reverse Hillis-Steele inclusive scan: s[i] = sum_{j>=i} hist[j]
    for (int off = 1; off < NBINS; off <<= 1) {
        int v[NBINS / 512];
        #pragma unroll
        for (int k = 0; k < NBINS / 512; k++) {
            int i = threadIdx.x + k * T;
            int j = i + off;
            v[k] = (j < NBINS) ? s[j] : 0;
        }
        __syncthreads();
        #pragma unroll
        for (int k = 0; k < NBINS / 512; k++)
            s[threadIdx.x + k * T] += v[k];
        __syncthreads();
    }
    if (threadIdx.x == 0) g_T[b] = 0;   // default: take everything
    __syncthreads();
    #pragma unroll
    for (int k = 0; k < NBINS / 512; k++) {
        int i = threadIdx.x + k * T;
        if (s[i] >= TOPK_N && (i == NBINS - 1 || s[i + 1] < TOPK_N))
            g_T[b] = i;                 // unique (s is non-increasing)
    }
}

// ---------------- kernel 3: compact candidates with bin >= T (smem-staged) ----------------
// key = (score_bits << 32) | (0xFFFFFFFF - flat_idx)  -> descending sort ==
// top_k order (score desc, index-ascending tiebreak)
__global__ void k_compact(const float* __restrict__ x) {
    __shared__ float tl[TILE * NCH];
    int b = blockIdx.y;
    int T = g_T[b];
    int box0 = blockIdx.x * TILE;

    size_t base = ((size_t)b * NBOX + (size_t)box0) * NCH;
    const float4* src = (const float4*)(x + base);
    float4* dst = (float4*)tl;
    #pragma unroll
    for (int i = threadIdx.x; i < TILE * NCH / 4; i += 256) dst[i] = src[i];
    __syncthreads();

    for (int it = threadIdx.x; it < TILE * NC; it += 256) {
        int box = it / NC;
        int c = it - box * NC;
        float obj = tl[box * NCH + 4];
        float s = __fmul_rn(tl[box * NCH + 5 + c], obj);
        if (obj > CONF && s > CONF) {
            unsigned bits = __float_as_uint(s);
            int bin = (int)(bits >> 12) - 0x3E800;
            bin = min(max(bin, 0), NBINS - 1);
            if (bin >= T) {
                int pos = atomicAdd(&g_cnt[b], 1);
                if (pos < CAP) {
                    unsigned ent = (unsigned)((box0 + box) * NC + c);
                    g_cand[b][pos] =
                        ((unsigned long long)bits << 32) | (unsigned long long)(0xFFFFFFFFu - ent);
                }
            }
        }
    }
}

// ---------------- kernel 4: bitonic sort candidates + gather top-1000 ----------------
__global__ void k_sortgather(const float* __restrict__ x) {
    int b = blockIdx.x;
    __shared__ unsigned long long key[CAP];
    int cnt = min(g_cnt[b], CAP);
    // runtime bitonic size: smallest pow2 >= cnt (>= 1024 to cover TOPK_N)
    unsigned npow = (cnt <= 1024) ? 1024u : ((cnt <= 2048) ? 2048u : 4096u);

    for (unsigned i = threadIdx.x; i < npow; i += blockDim.x)
        key[i] = (i < (unsigned)cnt) ? g_cand[b][i] : 0ULL;
    __syncthreads();

    for (unsigned k = 2; k <= npow; k <<= 1) {
        for (unsigned j = k >> 1; j > 0; j >>= 1) {
            for (unsigned i = threadIdx.x; i < npow; i += blockDim.x) {
                unsigned ixj = i ^ j;
                if (ixj > i) {
                    unsigned long long a = key[i], c2 = key[ixj];
                    bool descBlock = ((i & k) == 0);
                    bool doswap = descBlock ? (a < c2) : (a > c2);
                    if (doswap) { key[i] = c2; key[ixj] = a; }
                }
            }
            __syncthreads();
        }
    }

    for (int t = threadIdx.x; t < TOPK_N; t += blockDim.x) {
        unsigned long long kk = key[t];
        unsigned bits = (unsigned)(kk >> 32);
        float s, x1, y1, x2, y2, cf;
        if (bits) {
            unsigned ent = 0xFFFFFFFFu - (unsigned)(kk & 0xFFFFFFFFull);
            int bi = (int)(ent / NC);
            int ci = (int)(ent - (unsigned)bi * NC);
            const float* p = x + ((size_t)b * NBOX + bi) * NCH;
            float cx = p[0], cy = p[1], w = p[2], h = p[3];
            x1 = cx - 0.5f * w;  y1 = cy - 0.5f * h;
            x2 = cx + 0.5f * w;  y2 = cy + 0.5f * h;
            cf = (float)ci;
            s = __uint_as_float(bits);
        } else {
            x1 = y1 = x2 = y2 = 0.f; cf = 0.f; s = 0.f;
        }
        g_selbox[b][t] = make_float4(x1, y1, x2, y2);
        g_score[b][t] = s;
        g_cls[b][t] = cf;
        float off = cf * MAXWH;
        g_offbox[b][t] = make_float4(x1 + off, y1 + off, x2 + off, y2 + off);
    }
}

// ---------------- kernel 5: IoU suppression bitmask (j > i) ----------------
__global__ void k_mask() {
    int b = blockIdx.y;
    __shared__ float4 sbox[TOPK_N];
    for (int i = threadIdx.x; i < TOPK_N; i += blockDim.x)
        sbox[i] = g_offbox[b][i];
    __syncthreads();

    int unit = blockIdx.x * blockDim.x + threadIdx.x;
    int row = unit >> 5, word = unit & 31;
    if (row >= TOPK_N) return;
    float4 a = sbox[row];
    float aarea = __fmul_rn(__fsub_rn(a.z, a.x), __fsub_rn(a.w, a.y));
    unsigned bits = 0;
    int jbase = word * 32;
    #pragma unroll 8
    for (int t = 0; t < 32; t++) {
        int j = jbase + t;
        if (j < TOPK_N && j > row) {
            float4 c = sbox[j];
            float ix1 = fmaxf(a.x, c.x);
            float iy1 = fmaxf(a.y, c.y);
            float ix2 = fminf(a.z, c.z);
            float iy2 = fminf(a.w, c.w);
            float iw = fmaxf(__fsub_rn(ix2, ix1), 0.0f);
            float ih = fmaxf(__fsub_rn(iy2, iy1), 0.0f);
            float inter = __fmul_rn(iw, ih);
            float carea = __fmul_rn(__fsub_rn(c.z, c.x), __fsub_rn(c.w, c.y));
            float uni = __fsub_rn(__fadd_rn(aarea, carea), inter);
            float iou = __fdiv_rn(inter, fmaxf(uni, 1e-9f));
            if (iou > IOU_T) bits |= (1u << t);
        }
    }
    g_mask[b][row][word] = bits;
}

// ---------------- kernel 6: sequential suppression + ranked output ----------------
// dynamic smem: TOPK_N*32 unsigned = 128000 B (full per-image mask)
extern __shared__ unsigned s_mask[];
__global__ void k_nms(float* __restrict__ out) {
    int b = blockIdx.x;
    __shared__ unsigned s_keep[32];
    __shared__ int s_rank[TOPK_N];

    for (int i = threadIdx.x; i < TOPK_N * 32; i += blockDim.x)
        s_mask[i] = ((const unsigned*)g_mask[b])[i];
    __syncthreads();

    if (threadIdx.x < 32) {
        int l = threadIdx.x;
        unsigned myrem = 0;                 // lane l owns removal word l
        for (int j = 0; j < 32; j++) {
            int it = l * 32 + j;
            bool dead = (it >= TOPK_N) || !(g_score[b][it] > 0.0f);
            if (dead) myrem |= (1u << j);
        }
        unsigned mykeep = 0;
        for (int i = 0; i < TOPK_N; i++) {
            unsigned w = __shfl_sync(0xffffffffu, myrem, i >> 5);
            if (!((w >> (i & 31)) & 1u)) {
                myrem |= s_mask[i * 32 + l];
                if (l == (i >> 5)) mykeep |= (1u << (i & 31));
            }
        }
        s_keep[l] = mykeep;
    }
    __syncthreads();

    if (threadIdx.x == 0) {
        int r = 0;
        for (int i = 0; i < TOPK_N; i++) {
            bool kp = (s_keep[i >> 5] >> (i & 31)) & 1u;
            s_rank[i] = kp ? r : MAXDET;
            if (kp) r++;
        }
    }
    __syncthreads();

    for (int t = threadIdx.x; t < TOPK_N; t += blockDim.x) {
        int r = s_rank[t];
        if (r < MAXDET) {
            float4 bx = g_selbox[b][t];
            float* o = out + ((size_t)b * MAXDET + r) * 6;
            o[0] = bx.x; o[1] = bx.y; o[2] = bx.z; o[3] = bx.w;
            o[4] = g_score[b][t];
            o[5] = g_cls[b][t];
        }
    }
}

// ---------------- launch ----------------
extern "C" void kernel_launch(void* const* d_in, const int* in_sizes, int n_in,
                              void* d_out, int out_size) {
    (void)in_sizes; (void)n_in; (void)out_size;
    const float* x = (const float*)d_in[0];
    float* out = (float*)d_out;

    cudaFuncSetAttribute(k_nms, cudaFuncAttributeMaxDynamicSharedMemorySize, 132 * 1024);

    int zeroN = NIMG * NBINS;   // 65536 threads covers hist + cnt + out
    k_zero<<<(zeroN + 255) / 256, 256>>>(out);

    dim3 gh(NBOX / TILE, NIMG);            // 525 x 16
    k_hist<<<gh, 256>>>(x);
    k_thresh<<<NIMG, 512>>>();
    k_compact<<<gh, 256>>>(x);
    k_sortgather<<<NIMG, 512>>>(x);
    dim3 gm((TOPK_N * 32 + 255) / 256, NIMG);
    k_mask<<<gm, 256>>>();
    k_nms<<<NIMG, 128, TOPK_N * 32 * sizeof(unsigned)>>>(out);
}

// round 3
// speedup vs baseline: 1.5136x; 1.5136x over previous
#include <cuda_runtime.h>
#include <cstdint>

typedef unsigned long long u64;

#define NIMG   16
#define NBOX   25200
#define NCH    85
#define NC     80
#define NBINS  4096
#define CAP    4096
#define TOPK_N 1000
#define MAXDET 300
#define CONF   0.25f
#define IOU_T  0.45f
#define MAXWH  4096.0f
#define TILE   48                  // 25200 = 525*48
#define NTILES (NBOX / TILE)       // 525
#define PREBIN 3686                // bin of score 0.90
#define PRECAP 24576

// ---------------- scratch (static device memory) ----------------
__device__ int g_hist[NIMG][NBINS];
__device__ int g_precnt[NIMG];
__device__ int g_cnt[NIMG];
__device__ int g_T[NIMG];
__device__ int g_ok[NIMG];
__device__ u64 g_pre[NIMG][PRECAP];
__device__ u64 g_cand[NIMG][CAP];

// ---------------- kernel 0: zero scratch + output ----------------
__global__ void k_zero(float* __restrict__ out) {
    int i = blockIdx.x * blockDim.x + threadIdx.x;
    if (i < NIMG * NBINS) ((int*)g_hist)[i] = 0;
    if (i < NIMG) { g_precnt[i] = 0; g_cnt[i] = 0; }
    if (i < NIMG * MAXDET * 6) out[i] = 0.0f;
}

// ---------------- kernel 1: histogram + prefilter (single full pass) ----------------
// bin = (bits >> 12) - 0x3E800 : monotone map of score in (0.25,1) -> [0,4095]
__global__ void k_hist(const float* __restrict__ x) {
    __shared__ float tl[TILE * NCH];
    __shared__ int   sh[NBINS];
    int b = blockIdx.y;
    for (int i = threadIdx.x; i < NBINS; i += 256) sh[i] = 0;

    size_t base = ((size_t)b * NBOX + (size_t)blockIdx.x * TILE) * NCH;
    const float4* src = (const float4*)(x + base);
    float4* dst = (float4*)tl;
    for (int i = threadIdx.x; i < TILE * NCH / 4; i += 256) dst[i] = src[i];
    __syncthreads();

    int warp = threadIdx.x >> 5, lane = threadIdx.x & 31;
    int box0 = blockIdx.x * TILE;
    for (int box = warp; box < TILE; box += 8) {
        float obj = tl[box * NCH + 4];
        if (obj <= CONF) continue;           // warp-uniform
        #pragma unroll
        for (int k = 0; k < 3; k++) {
            int c = k * 32 + lane;
            bool pre = false; unsigned bits = 0;
            if (c < NC) {
                float s = __fmul_rn(tl[box * NCH + 5 + c], obj);
                if (s > CONF) {
                    bits = __float_as_uint(s);
                    int bin = (int)(bits >> 12) - 0x3E800;
                    atomicAdd(&sh[bin], 1);
                    pre = (bin >= PREBIN);
                }
            }
            unsigned m = __ballot_sync(0xffffffffu, pre);
            if (m) {
                int leader = __ffs(m) - 1;
                int basep = 0;
                if (lane == leader) basep = atomicAdd(&g_precnt[b], __popc(m));
                basep = __shfl_sync(0xffffffffu, basep, leader);
                if (pre) {
                    int pos = basep + __popc(m & ((1u << lane) - 1u));
                    if (pos < PRECAP) {
                        unsigned ent = (unsigned)((box0 + box) * NC + c);
                        g_pre[b][pos] = ((u64)bits << 32) | (u64)(0xFFFFFFFFu - ent);
                    }
                }
            }
        }
    }
    __syncthreads();
    for (int i = threadIdx.x; i < NBINS; i += 256)
        if (sh[i]) atomicAdd(&g_hist[b][i], sh[i]);
}

// ---------------- kernel 2: suffix scan -> exact threshold bin + ok flag ----------------
__global__ void k_thresh() {
    int b = blockIdx.x;
    __shared__ int s[NBINS];
    __shared__ int sT;
    const int T = 512;
    for (int i = threadIdx.x; i < NBINS; i += T) s[i] = g_hist[b][i];
    if (threadIdx.x == 0) sT = 0;
    __syncthreads();
    for (int off = 1; off < NBINS; off <<= 1) {
        int v[NBINS / 512];
        #pragma unroll
        for (int k = 0; k < NBINS / 512; k++) {
            int i = threadIdx.x + k * T;
            int j = i + off;
            v[k] = (j < NBINS) ? s[j] : 0;
        }
        __syncthreads();
        #pragma unroll
        for (int k = 0; k < NBINS / 512; k++)
            s[threadIdx.x + k * T] += v[k];
        __syncthreads();
    }
    #pragma unroll
    for (int k = 0; k < NBINS / 512; k++) {
        int i = threadIdx.x + k * T;
        if (s[i] >= TOPK_N && (i == NBINS - 1 || s[i + 1] < TOPK_N))
            sT = i;                        // unique (non-increasing suffix)
    }
    __syncthreads();
    if (threadIdx.x == 0) {
        g_T[b] = sT;
        g_ok[b] = (sT >= PREBIN) && (g_precnt[b] <= PRECAP);
    }
}

// ---------------- kernel 3: FALLBACK full-scan compact (no-op when prefilter ok) ----------------
__global__ void k_compact_full(const float* __restrict__ x) {
    int b = blockIdx.y;
    if (g_ok[b]) return;                   // fast exit, uniform per block
    int T = g_T[b];
    __shared__ float tl[TILE * NCH];
    for (int tile = blockIdx.x; tile < NTILES; tile += gridDim.x) {
        __syncthreads();
        size_t base = ((size_t)b * NBOX + (size_t)tile * TILE) * NCH;
        const float4* src = (const float4*)(x + base);
        float4* dst = (float4*)tl;
        for (int i = threadIdx.x; i < TILE * NCH / 4; i += 256) dst[i] = src[i];
        __syncthreads();
        for (int it = threadIdx.x; it < TILE * NC; it += 256) {
            int box = it / NC;
            int c = it - box * NC;
            float obj = tl[box * NCH + 4];
            float s = __fmul_rn(tl[box * NCH + 5 + c], obj);
            if (obj > CONF && s > CONF) {
                unsigned bits = __float_as_uint(s);
                int bin = (int)(bits >> 12) - 0x3E800;
                if (bin >= T) {
                    int pos = atomicAdd(&g_cnt[b], 1);
                    if (pos < CAP) {
                        unsigned ent = (unsigned)((tile * TILE + box) * NC + c);
                        g_cand[b][pos] = ((u64)bits << 32) | (u64)(0xFFFFFFFFu - ent);
                    }
                }
            }
        }
    }
}

// ---------------- kernel 4: fused select + sort + gather + per-class NMS + output ----------------
// dynamic smem layout
#define OFF_KEY   0                         // u64[4096]          32768
#define OFF_OFFB  32768                     // float4[1024]       16384
#define OFF_SELB  49152                     // float4[1024]       16384
#define OFF_SCORE 65536                     // float[1024]         4096
#define OFF_KEEP  69632                     // int[1024]           4096
#define OFF_CLS   73728                     // ushort[1024]        2048
#define OFF_LIST  75776                     // ushort[1024]        2048
#define OFF_CCNT  77824                     // int[80]              320
#define OFF_COFF  78144                     // int[80]              320
#define OFF_WSUM  78464                     // int[32]              128
#define SMEM_FINAL 78592

__global__ void k_final(const float* __restrict__ x, float* __restrict__ out) {
    extern __shared__ unsigned char sm[];
    u64*            key  = (u64*)(sm + OFF_KEY);
    float4*         offb = (float4*)(sm + OFF_OFFB);
    float4*         selb = (float4*)(sm + OFF_SELB);
    float*          scr  = (float*)(sm + OFF_SCORE);
    int*            keep = (int*)(sm + OFF_KEEP);
    unsigned short* cls  = (unsigned short*)(sm + OFF_CLS);
    unsigned short* list = (unsigned short*)(sm + OFF_LIST);
    int*            ccnt = (int*)(sm + OFF_CCNT);
    int*            coff = (int*)(sm + OFF_COFF);
    int*            wsum = (int*)(sm + OFF_WSUM);
    __shared__ int cnt_s;

    int b = blockIdx.x;
    int tid = threadIdx.x;              // 0..1023
    int lane = tid & 31, warp = tid >> 5;

    for (int i = tid; i < CAP; i += 1024) key[i] = 0ULL;
    if (tid == 0) cnt_s = 0;
    __syncthreads();

    // ---- select candidates with bin >= T ----
    if (g_ok[b]) {
        int T = g_T[b];
        int pn = min(g_precnt[b], PRECAP);
        for (int i0 = 0; i0 < pn; i0 += 1024) {
            int i = i0 + tid;
            bool take = false; u64 kk = 0;
            if (i < pn) {
                kk = g_pre[b][i];
                int bin = (int)(kk >> 44) - 0x3E800;
                take = (bin >= T);
            }
            unsigned m = __ballot_sync(0xffffffffu, take);
            if (m) {
                int leader = __ffs(m) - 1;
                int basep = 0;
                if (lane == leader) basep = atomicAdd(&cnt_s, __popc(m));
                basep = __shfl_sync(0xffffffffu, basep, leader);
                if (take) {
                    int pos = basep + __popc(m & ((1u << lane) - 1u));
                    if (pos < CAP) key[pos] = kk;
                }
            }
        }
    } else {
        int n = min(g_cnt[b], CAP);
        for (int i = tid; i < n; i += 1024) key[i] = g_cand[b][i];
        if (tid == 0) cnt_s = n;
    }
    __syncthreads();
    int cnt = min(cnt_s, CAP);
    unsigned npow = (cnt <= 1024) ? 1024u : ((cnt <= 2048) ? 2048u : 4096u);

    // ---- bitonic sort descending (key = score_bits:~idx) ----
    for (unsigned k = 2; k <= npow; k <<= 1) {
        for (unsigned j = k >> 1; j > 0; j >>= 1) {
            for (unsigned i = tid; i < npow; i += 1024) {
                unsigned ixj = i ^ j;
                if (ixj > i) {
                    u64 a = key[i], c2 = key[ixj];
                    bool descBlock = ((i & k) == 0);
                    if (descBlock ? (a < c2) : (a > c2)) { key[i] = c2; key[ixj] = a; }
                }
            }
            __syncthreads();
        }
    }

    // ---- gather top-1000: boxes, scores, classes (same numeric path as R2) ----
    if (tid < TOPK_N) {
        u64 kk = key[tid];
        unsigned bits = (unsigned)(kk >> 32);
        float s, x1, y1, x2, y2, cf; int ci = 0;
        if (bits) {
            unsigned ent = 0xFFFFFFFFu - (unsigned)(kk & 0xFFFFFFFFull);
            int bi = (int)(ent / NC);
            ci = (int)(ent - (unsigned)bi * NC);
            const float* p = x + ((size_t)b * NBOX + bi) * NCH;
            float cx = p[0], cy = p[1], w = p[2], h = p[3];
            x1 = cx - 0.5f * w;  y1 = cy - 0.5f * h;
            x2 = cx + 0.5f * w;  y2 = cy + 0.5f * h;
            cf = (float)ci;
            s = __uint_as_float(bits);
        } else {
            x1 = y1 = x2 = y2 = 0.f; cf = 0.f; s = 0.f;
        }
        selb[tid] = make_float4(x1, y1, x2, y2);
        scr[tid] = s;
        cls[tid] = (unsigned short)ci;
        float off = cf * MAXWH;
        offb[tid] = make_float4(x1 + off, y1 + off, x2 + off, y2 + off);
    }
    keep[tid] = 0;
    __syncthreads();

    // ---- per-class member lists (stable, ascending t) ----
    for (int c = warp; c < NC; c += 32) {           // warp handles class c
        int cc = 0;
        for (int ch = 0; ch < 32; ch++) {
            int t = ch * 32 + lane;
            bool mem = (t < TOPK_N) && (scr[t] > 0.0f) && ((int)cls[t] == c);
            cc += __popc(__ballot_sync(0xffffffffu, mem));
        }
        if (lane == 0) ccnt[c] = cc;
    }
    __syncthreads();
    if (tid == 0) { int a = 0; for (int c = 0; c < NC; c++) { coff[c] = a; a += ccnt[c]; } }
    __syncthreads();
    for (int c = warp; c < NC; c += 32) {
        int p = coff[c];
        for (int ch = 0; ch < 32; ch++) {
            int t = ch * 32 + lane;
            bool mem = (t < TOPK_N) && (scr[t] > 0.0f) && ((int)cls[t] == c);
            unsigned m = __ballot_sync(0xffffffffu, mem);
            if (mem) list[p + __popc(m & ((1u << lane) - 1u))] = (unsigned short)t;
            p += __popc(m);
        }
    }
    __syncthreads();

    // ---- greedy NMS per class (warp-parallel; cross-class IoU is exactly 0) ----
    for (int c = warp; c < NC; c += 32) {
        int m = ccnt[c], base = coff[c];
        unsigned sup = 0;                 // lane l owns slots q with q%32==l, bit q>>5
        for (int p = 0; p < m; p++) {
            unsigned w = __shfl_sync(0xffffffffu, sup, p & 31);
            if ((w >> (p >> 5)) & 1u) continue;     // pivot suppressed (uniform)
            int tp = list[base + p];
            if (lane == 0) keep[tp] = 1;
            float4 a = offb[tp];
            float aarea = __fmul_rn(__fsub_rn(a.z, a.x), __fsub_rn(a.w, a.y));
            for (int q = lane; q < m; q += 32) {
                if (q > p && !((sup >> (q >> 5)) & 1u)) {
                    float4 cb = offb[list[base + q]];
                    float ix1 = fmaxf(a.x, cb.x);
                    float iy1 = fmaxf(a.y, cb.y);
                    float ix2 = fminf(a.z, cb.z);
                    float iy2 = fminf(a.w, cb.w);
                    float iw = fmaxf(__fsub_rn(ix2, ix1), 0.0f);
                    float ih = fmaxf(__fsub_rn(iy2, iy1), 0.0f);
                    float inter = __fmul_rn(iw, ih);
                    float carea = __fmul_rn(__fsub_rn(cb.z, cb.x), __fsub_rn(cb.w, cb.y));
                    float uni = __fsub_rn(__fadd_rn(aarea, carea), inter);
                    float iou = __fdiv_rn(inter, fmaxf(uni, 1e-9f));
                    if (iou > IOU_T) sup |= 1u << (q >> 5);
                }
            }
        }
    }
    __syncthreads();

    // ---- rank kept entries (block scan) + write output ----
    int flag = (tid < TOPK_N) ? keep[tid] : 0;
    int v = flag;
    #pragma unroll
    for (int o = 1; o < 32; o <<= 1) {
        int u = __shfl_up_sync(0xffffffffu, v, o);
        if (lane >= o) v += u;
    }
    if (lane == 31) wsum[warp] = v;
    __syncthreads();
    if (warp == 0) {
        int ws = wsum[lane];
        #pragma unroll
        for (int o = 1; o < 32; o <<= 1) {
            int u = __shfl_up_sync(0xffffffffu, ws, o);
            if (lane >= o) ws += u;
        }
        wsum[lane] = ws;                  // inclusive
    }
    __syncthreads();
    int incl = v + (warp ? wsum[warp - 1] : 0);
    int r = incl - flag;                  // exclusive rank
    if (flag && r < MAXDET) {
        float4 bx = selb[tid];
        float* o = out + ((size_t)b * MAXDET + r) * 6;
        o[0] = bx.x; o[1] = bx.y; o[2] = bx.z; o[3] = bx.w;
        o[4] = scr[tid];
        o[5] = (float)cls[tid];
    }
}

// ---------------- launch ----------------
extern "C" void kernel_launch(void* const* d_in, const int* in_sizes, int n_in,
                              void* d_out, int out_size) {
    (void)in_sizes; (void)n_in; (void)out_size;
    const float* x = (const float*)d_in[0];
    float* out = (float*)d_out;

    cudaFuncSetAttribute(k_final, cudaFuncAttributeMaxDynamicSharedMemorySize, SMEM_FINAL);

    int zeroN = NIMG * NBINS;
    k_zero<<<(zeroN + 255) / 256, 256>>>(out);

    dim3 gh(NTILES, NIMG);                 // 525 x 16
    k_hist<<<gh, 256>>>(x);
    k_thresh<<<NIMG, 512>>>();
    k_compact_full<<<dim3(132, NIMG), 256>>>(x);   // fallback; exits fast when ok
    k_final<<<NIMG, 1024, SMEM_FINAL>>>(x, out);
}

// round 4
// speedup vs baseline: 1.5139x; 1.0002x over previous
#include <cuda_runtime.h>
#include <cstdint>

typedef unsigned long long u64;

#define NIMG   16
#define NBOX   25200
#define NCH    85
#define NC     80
#define NBINS  4096
#define CAP    4096
#define TOPK_N 1000
#define MAXDET 300
#define CONF   0.25f
#define IOU_T  0.45f
#define MAXWH  4096.0f
#define TILE   48                  // 25200 = 525*48
#define NTILES (NBOX / TILE)       // 525
#define PREBIN 3686                // bin of score 0.90
#define PRECAP 24576

// ---------------- scratch (static device memory) ----------------
__device__ int g_hist[NIMG][NBINS];
__device__ int g_precnt[NIMG];
__device__ int g_cnt[NIMG];
__device__ int g_T[NIMG];
__device__ int g_ok[NIMG];
__device__ u64 g_pre[NIMG][PRECAP];
__device__ u64 g_cand[NIMG][CAP];

// ---------------- kernel 0: zero scratch + output ----------------
__global__ void k_zero(float* __restrict__ out) {
    int i = blockIdx.x * blockDim.x + threadIdx.x;
    if (i < NIMG * NBINS) ((int*)g_hist)[i] = 0;
    if (i < NIMG) { g_precnt[i] = 0; g_cnt[i] = 0; }
    if (i < NIMG * MAXDET * 6) out[i] = 0.0f;
}

// ---------------- kernel 1: histogram + prefilter (single full pass) ----------------
// bin = (bits >> 12) - 0x3E800 : monotone map of score in (0.25,1) -> [0,4095]
__global__ void k_hist(const float* __restrict__ x) {
    __shared__ float tl[TILE * NCH];
    __shared__ int   sh[NBINS];
    int b = blockIdx.y;
    for (int i = threadIdx.x; i < NBINS; i += 256) sh[i] = 0;

    size_t base = ((size_t)b * NBOX + (size_t)blockIdx.x * TILE) * NCH;
    const float4* src = (const float4*)(x + base);
    float4* dst = (float4*)tl;
    for (int i = threadIdx.x; i < TILE * NCH / 4; i += 256) dst[i] = src[i];
    __syncthreads();

    int warp = threadIdx.x >> 5, lane = threadIdx.x & 31;
    int box0 = blockIdx.x * TILE;
    for (int box = warp; box < TILE; box += 8) {
        float obj = tl[box * NCH + 4];
        if (obj <= CONF) continue;           // warp-uniform
        #pragma unroll
        for (int k = 0; k < 3; k++) {
            int c = k * 32 + lane;
            bool pre = false; unsigned bits = 0;
            if (c < NC) {
                float s = __fmul_rn(tl[box * NCH + 5 + c], obj);
                if (s > CONF) {
                    bits = __float_as_uint(s);
                    int bin = (int)(bits >> 12) - 0x3E800;
                    atomicAdd(&sh[bin], 1);
                    pre = (bin >= PREBIN);
                }
            }
            unsigned m = __ballot_sync(0xffffffffu, pre);
            if (m) {
                int leader = __ffs(m) - 1;
                int basep = 0;
                if (lane == leader) basep = atomicAdd(&g_precnt[b], __popc(m));
                basep = __shfl_sync(0xffffffffu, basep, leader);
                if (pre) {
                    int pos = basep + __popc(m & ((1u << lane) - 1u));
                    if (pos < PRECAP) {
                        unsigned ent = (unsigned)((box0 + box) * NC + c);
                        g_pre[b][pos] = ((u64)bits << 32) | (u64)(0xFFFFFFFFu - ent);
                    }
                }
            }
        }
    }
    __syncthreads();
    for (int i = threadIdx.x; i < NBINS; i += 256)
        if (sh[i]) atomicAdd(&g_hist[b][i], sh[i]);
}

// ---------------- kernel 2: suffix scan -> exact threshold bin + ok flag ----------------
__global__ void k_thresh() {
    int b = blockIdx.x;
    __shared__ int s[NBINS];
    __shared__ int sT;
    const int T = 512;
    for (int i = threadIdx.x; i < NBINS; i += T) s[i] = g_hist[b][i];
    if (threadIdx.x == 0) sT = 0;
    __syncthreads();
    for (int off = 1; off < NBINS; off <<= 1) {
        int v[NBINS / 512];
        #pragma unroll
        for (int k = 0; k < NBINS / 512; k++) {
            int i = threadIdx.x + k * T;
            int j = i + off;
            v[k] = (j < NBINS) ? s[j] : 0;
        }
        __syncthreads();
        #pragma unroll
        for (int k = 0; k < NBINS / 512; k++)
            s[threadIdx.x + k * T] += v[k];
        __syncthreads();
    }
    #pragma unroll
    for (int k = 0; k < NBINS / 512; k++) {
        int i = threadIdx.x + k * T;
        if (s[i] >= TOPK_N && (i == NBINS - 1 || s[i + 1] < TOPK_N))
            sT = i;                        // unique (non-increasing suffix)
    }
    __syncthreads();
    if (threadIdx.x == 0) {
        g_T[b] = sT;
        g_ok[b] = (sT >= PREBIN) && (g_precnt[b] <= PRECAP);
    }
}

// ---------------- kernel 3: FALLBACK full-scan compact (no-op when prefilter ok) ----------------
__global__ void k_compact_full(const float* __restrict__ x) {
    int b = blockIdx.y;
    if (g_ok[b]) return;                   // fast exit, uniform per block
    int T = g_T[b];
    __shared__ float tl[TILE * NCH];
    for (int tile = blockIdx.x; tile < NTILES; tile += gridDim.x) {
        __syncthreads();
        size_t base = ((size_t)b * NBOX + (size_t)tile * TILE) * NCH;
        const float4* src = (const float4*)(x + base);
        float4* dst = (float4*)tl;
        for (int i = threadIdx.x; i < TILE * NCH / 4; i += 256) dst[i] = src[i];
        __syncthreads();
        for (int it = threadIdx.x; it < TILE * NC; it += 256) {
            int box = it / NC;
            int c = it - box * NC;
            float obj = tl[box * NCH + 4];
            float s = __fmul_rn(tl[box * NCH + 5 + c], obj);
            if (obj > CONF && s > CONF) {
                unsigned bits = __float_as_uint(s);
                int bin = (int)(bits >> 12) - 0x3E800;
                if (bin >= T) {
                    int pos = atomicAdd(&g_cnt[b], 1);
                    if (pos < CAP) {
                        unsigned ent = (unsigned)((tile * TILE + box) * NC + c);
                        g_cand[b][pos] = ((u64)bits << 32) | (u64)(0xFFFFFFFFu - ent);
                    }
                }
            }
        }
    }
}

// ---------------- kernel 4: fused select + sort + gather + per-class NMS + output ----------------
// dynamic smem layout
#define OFF_KEY   0                         // u64[4096]          32768
#define OFF_OFFB  32768                     // float4[1024]       16384
#define OFF_SELB  49152                     // float4[1024]       16384
#define OFF_SCORE 65536                     // float[1024]         4096
#define OFF_KEEP  69632                     // int[1024]           4096
#define OFF_CLS   73728                     // ushort[1024]        2048
#define OFF_LIST  75776                     // ushort[1024]        2048
#define OFF_CCNT  77824                     // int[80]              320
#define OFF_COFF  78144                     // int[80]              320
#define OFF_WSUM  78464                     // int[32]              128
#define SMEM_FINAL 78592

__global__ void k_final(const float* __restrict__ x, float* __restrict__ out) {
    extern __shared__ unsigned char sm[];
    u64*            key  = (u64*)(sm + OFF_KEY);
    float4*         offb = (float4*)(sm + OFF_OFFB);
    float4*         selb = (float4*)(sm + OFF_SELB);
    float*          scr  = (float*)(sm + OFF_SCORE);
    int*            keep = (int*)(sm + OFF_KEEP);
    unsigned short* cls  = (unsigned short*)(sm + OFF_CLS);
    unsigned short* list = (unsigned short*)(sm + OFF_LIST);
    int*            ccnt = (int*)(sm + OFF_CCNT);
    int*            coff = (int*)(sm + OFF_COFF);
    int*            wsum = (int*)(sm + OFF_WSUM);
    __shared__ int cnt_s;

    int b = blockIdx.x;
    int tid = threadIdx.x;              // 0..1023
    int lane = tid & 31, warp = tid >> 5;

    for (int i = tid; i < CAP; i += 1024) key[i] = 0ULL;
    if (tid == 0) cnt_s = 0;
    __syncthreads();

    // ---- select candidates with bin >= T ----
    if (g_ok[b]) {
        int T = g_T[b];
        int pn = min(g_precnt[b], PRECAP);
        for (int i0 = 0; i0 < pn; i0 += 1024) {
            int i = i0 + tid;
            bool take = false; u64 kk = 0;
            if (i < pn) {
                kk = g_pre[b][i];
                int bin = (int)(kk >> 44) - 0x3E800;
                take = (bin >= T);
            }
            unsigned m = __ballot_sync(0xffffffffu, take);
            if (m) {
                int leader = __ffs(m) - 1;
                int basep = 0;
                if (lane == leader) basep = atomicAdd(&cnt_s, __popc(m));
                basep = __shfl_sync(0xffffffffu, basep, leader);
                if (take) {
                    int pos = basep + __popc(m & ((1u << lane) - 1u));
                    if (pos < CAP) key[pos] = kk;
                }
            }
        }
    } else {
        int n = min(g_cnt[b], CAP);
        for (int i = tid; i < n; i += 1024) key[i] = g_cand[b][i];
        if (tid == 0) cnt_s = n;
    }
    __syncthreads();
    int cnt = min(cnt_s, CAP);
    unsigned npow = (cnt <= 1024) ? 1024u : ((cnt <= 2048) ? 2048u : 4096u);

    // ---- bitonic sort descending (key = score_bits:~idx) ----
    for (unsigned k = 2; k <= npow; k <<= 1) {
        for (unsigned j = k >> 1; j > 0; j >>= 1) {
            for (unsigned i = tid; i < npow; i += 1024) {
                unsigned ixj = i ^ j;
                if (ixj > i) {
                    u64 a = key[i], c2 = key[ixj];
                    bool descBlock = ((i & k) == 0);
                    if (descBlock ? (a < c2) : (a > c2)) { key[i] = c2; key[ixj] = a; }
                }
            }
            __syncthreads();
        }
    }

    // ---- gather top-1000: boxes, scores, classes (same numeric path as R2) ----
    if (tid < TOPK_N) {
        u64 kk = key[tid];
        unsigned bits = (unsigned)(kk >> 32);
        float s, x1, y1, x2, y2, cf; int ci = 0;
        if (bits) {
            unsigned ent = 0xFFFFFFFFu - (unsigned)(kk & 0xFFFFFFFFull);
            int bi = (int)(ent / NC);
            ci = (int)(ent - (unsigned)bi * NC);
            const float* p = x + ((size_t)b * NBOX + bi) * NCH;
            float cx = p[0], cy = p[1], w = p[2], h = p[3];
            x1 = cx - 0.5f * w;  y1 = cy - 0.5f * h;
            x2 = cx + 0.5f * w;  y2 = cy + 0.5f * h;
            cf = (float)ci;
            s = __uint_as_float(bits);
        } else {
            x1 = y1 = x2 = y2 = 0.f; cf = 0.f; s = 0.f;
        }
        selb[tid] = make_float4(x1, y1, x2, y2);
        scr[tid] = s;
        cls[tid] = (unsigned short)ci;
        float off = cf * MAXWH;
        offb[tid] = make_float4(x1 + off, y1 + off, x2 + off, y2 + off);
    }
    keep[tid] = 0;
    __syncthreads();

    // ---- per-class member lists (stable, ascending t) ----
    for (int c = warp; c < NC; c += 32) {           // warp handles class c
        int cc = 0;
        for (int ch = 0; ch < 32; ch++) {
            int t = ch * 32 + lane;
            bool mem = (t < TOPK_N) && (scr[t] > 0.0f) && ((int)cls[t] == c);
            cc += __popc(__ballot_sync(0xffffffffu, mem));
        }
        if (lane == 0) ccnt[c] = cc;
    }
    __syncthreads();
    if (tid == 0) { int a = 0; for (int c = 0; c < NC; c++) { coff[c] = a; a += ccnt[c]; } }
    __syncthreads();
    for (int c = warp; c < NC; c += 32) {
        int p = coff[c];
        for (int ch = 0; ch < 32; ch++) {
            int t = ch * 32 + lane;
            bool mem = (t < TOPK_N) && (scr[t] > 0.0f) && ((int)cls[t] == c);
            unsigned m = __ballot_sync(0xffffffffu, mem);
            if (mem) list[p + __popc(m & ((1u << lane) - 1u))] = (unsigned short)t;
            p += __popc(m);
        }
    }
    __syncthreads();

    // ---- greedy NMS per class (warp-parallel; cross-class IoU is exactly 0) ----
    for (int c = warp; c < NC; c += 32) {
        int m = ccnt[c], base = coff[c];
        unsigned sup = 0;                 // lane l owns slots q with q%32==l, bit q>>5
        for (int p = 0; p < m; p++) {
            unsigned w = __shfl_sync(0xffffffffu, sup, p & 31);
            if ((w >> (p >> 5)) & 1u) continue;     // pivot suppressed (uniform)
            int tp = list[base + p];
            if (lane == 0) keep[tp] = 1;
            float4 a = offb[tp];
            float aarea = __fmul_rn(__fsub_rn(a.z, a.x), __fsub_rn(a.w, a.y));
            for (int q = lane; q < m; q += 32) {
                if (q > p && !((sup >> (q >> 5)) & 1u)) {
                    float4 cb = offb[list[base + q]];
                    float ix1 = fmaxf(a.x, cb.x);
                    float iy1 = fmaxf(a.y, cb.y);
                    float ix2 = fminf(a.z, cb.z);
                    float iy2 = fminf(a.w, cb.w);
                    float iw = fmaxf(__fsub_rn(ix2, ix1), 0.0f);
                    float ih = fmaxf(__fsub_rn(iy2, iy1), 0.0f);
                    float inter = __fmul_rn(iw, ih);
                    float carea = __fmul_rn(__fsub_rn(cb.z, cb.x), __fsub_rn(cb.w, cb.y));
                    float uni = __fsub_rn(__fadd_rn(aarea, carea), inter);
                    float iou = __fdiv_rn(inter, fmaxf(uni, 1e-9f));
                    if (iou > IOU_T) sup |= 1u << (q >> 5);
                }
            }
        }
    }
    __syncthreads();

    // ---- rank kept entries (block scan) + write output ----
    int flag = (tid < TOPK_N) ? keep[tid] : 0;
    int v = flag;
    #pragma unroll
    for (int o = 1; o < 32; o <<= 1) {
        int u = __shfl_up_sync(0xffffffffu, v, o);
        if (lane >= o) v += u;
    }
    if (lane == 31) wsum[warp] = v;
    __syncthreads();
    if (warp == 0) {
        int ws = wsum[lane];
        #pragma unroll
        for (int o = 1; o < 32; o <<= 1) {
            int u = __shfl_up_sync(0xffffffffu, ws, o);
            if (lane >= o) ws += u;
        }
        wsum[lane] = ws;                  // inclusive
    }
    __syncthreads();
    int incl = v + (warp ? wsum[warp - 1] : 0);
    int r = incl - flag;                  // exclusive rank
    if (flag && r < MAXDET) {
        float4 bx = selb[tid];
        float* o = out + ((size_t)b * MAXDET + r) * 6;
        o[0] = bx.x; o[1] = bx.y; o[2] = bx.z; o[3] = bx.w;
        o[4] = scr[tid];
        o[5] = (float)cls[tid];
    }
}

// ---------------- launch ----------------
extern "C" void kernel_launch(void* const* d_in, const int* in_sizes, int n_in,
                              void* d_out, int out_size) {
    (void)in_sizes; (void)n_in; (void)out_size;
    const float* x = (const float*)d_in[0];
    float* out = (float*)d_out;

    cudaFuncSetAttribute(k_final, cudaFuncAttributeMaxDynamicSharedMemorySize, SMEM_FINAL);

    int zeroN = NIMG * NBINS;
    k_zero<<<(zeroN + 255) / 256, 256>>>(out);

    dim3 gh(NTILES, NIMG);                 // 525 x 16
    k_hist<<<gh, 256>>>(x);
    k_thresh<<<NIMG, 512>>>();
    k_compact_full<<<dim3(132, NIMG), 256>>>(x);   // fallback; exits fast when ok
    k_final<<<NIMG, 1024, SMEM_FINAL>>>(x, out);
}

// round 6
// speedup vs baseline: 1.8235x; 1.2045x over previous
#include <cuda_runtime.h>
#include <cstdint>

typedef unsigned long long u64;

#define NIMG   16
#define NBOX   25200
#define NCH    85
#define NC     80
#define NBINS  4096
#define CAP    4096
#define TOPK_N 1000
#define MAXDET 300
#define CONF   0.25f
#define IOU_T  0.45f
#define MAXWH  4096.0f
#define PREBIN 3686                 // bin of score 0.89998169 (bits 0x3F666000)
#define PRE_F  __uint_as_float(0x3F666000u)
#define PRECAP 24576

// ---------------- scratch (static device memory) ----------------
__device__ int g_precnt[NIMG];      // zero-initialized; reset by k_final each call
__device__ int g_T[NIMG];
__device__ int g_ok[NIMG];
__device__ u64 g_pre[NIMG][PRECAP];

// ---------------- kernel 1: prefilter pass (warp-per-box, obj-gated) ----------------
// collect (box,cls) with obj > CONF and score >= PRE_F as sortable keys
__global__ void k_pre(const float* __restrict__ x) {
    int b = blockIdx.y;
    int lane = threadIdx.x & 31;
    int gw = blockIdx.x * (blockDim.x >> 5) + (threadIdx.x >> 5);
    int W = gridDim.x * (blockDim.x >> 5);
    const float* xb = x + (size_t)b * NBOX * NCH;

    for (int box = gw; box < NBOX; box += W) {
        const float* p = xb + (size_t)box * NCH;
        float obj = p[4];                     // warp-uniform broadcast load
        if (obj <= CONF) continue;            // skip: class probs never read
        #pragma unroll
        for (int r = 0; r < 3; r++) {
            int c = r * 32 + lane;
            bool pre = false; unsigned bits = 0;
            if (c < NC) {
                float s = __fmul_rn(p[5 + c], obj);
                bits = __float_as_uint(s);
                pre = (s >= PRE_F);           // implies s > CONF; positive floats
            }
            unsigned m = __ballot_sync(0xffffffffu, pre);
            if (m) {
                int leader = __ffs(m) - 1;
                int basep = 0;
                if (lane == leader) basep = atomicAdd(&g_precnt[b], __popc(m));
                basep = __shfl_sync(0xffffffffu, basep, leader);
                if (pre) {
                    int pos = basep + __popc(m & ((1u << lane) - 1u));
                    if (pos < PRECAP) {
                        unsigned ent = (unsigned)(box * NC + c);
                        g_pre[b][pos] = ((u64)bits << 32) | (u64)(0xFFFFFFFFu - ent);
                    }
                }
            }
        }
    }
}

// ---------------- kernel 2: exact threshold (happy: from pre-list; else full scan) ----------------
__global__ void k_check(const float* __restrict__ x) {
    int b = blockIdx.x;
    int tid = threadIdx.x;                    // 512 threads
    __shared__ int sh[NBINS];
    __shared__ int sT;
    int pn_raw = g_precnt[b];
    bool ok0 = (pn_raw >= TOPK_N) && (pn_raw <= PRECAP);

    if (ok0) {
        // window histogram over bins [PREBIN, PREBIN+512) from the pre-list
        sh[tid] = 0;
        __syncthreads();
        for (int i = tid; i < pn_raw; i += 512) {
            unsigned bits = (unsigned)(g_pre[b][i] >> 32);
            int rel = (int)(bits >> 12) - (0x3E800 + PREBIN);
            atomicAdd(&sh[min(max(rel, 0), 511)], 1);
        }
        __syncthreads();
        // suffix scan over 512
        for (int off = 1; off < 512; off <<= 1) {
            int v = (tid + off < 512) ? sh[tid + off] : 0;
            __syncthreads();
            sh[tid] += v;
            __syncthreads();
        }
        if (tid == 0) sT = 0;
        __syncthreads();
        if (sh[tid] >= TOPK_N && (tid == 511 || sh[tid + 1] < TOPK_N)) sT = tid;
        __syncthreads();
        if (tid == 0) { g_T[b] = PREBIN + sT; g_ok[b] = 1; }
    } else {
        // FALLBACK (exact, slow; never taken on typical inputs): full histogram of image b
        for (int i = tid; i < NBINS; i += 512) sh[i] = 0;
        __syncthreads();
        int lane = tid & 31, warp = tid >> 5;
        const float* xb = x + (size_t)b * NBOX * NCH;
        for (int box = warp; box < NBOX; box += 16) {
            const float* p = xb + (size_t)box * NCH;
            float obj = p[4];
            if (obj <= CONF) continue;
            #pragma unroll
            for (int r = 0; r < 3; r++) {
                int c = r * 32 + lane;
                if (c < NC) {
                    float s = __fmul_rn(p[5 + c], obj);
                    if (s > CONF) {
                        int bin = (int)(__float_as_uint(s) >> 12) - 0x3E800;
                        atomicAdd(&sh[min(max(bin, 0), NBINS - 1)], 1);
                    }
                }
            }
        }
        __syncthreads();
        // suffix scan over 4096 (8 per thread)
        for (int off = 1; off < NBINS; off <<= 1) {
            int v[NBINS / 512];
            #pragma unroll
            for (int k = 0; k < NBINS / 512; k++) {
                int i = tid + k * 512;
                int j = i + off;
                v[k] = (j < NBINS) ? sh[j] : 0;
            }
            __syncthreads();
            #pragma unroll
            for (int k = 0; k < NBINS / 512; k++) sh[tid + k * 512] += v[k];
            __syncthreads();
        }
        if (tid == 0) sT = 0;
        __syncthreads();
        #pragma unroll
        for (int k = 0; k < NBINS / 512; k++) {
            int i = tid + k * 512;
            if (sh[i] >= TOPK_N && (i == NBINS - 1 || sh[i + 1] < TOPK_N)) sT = i;
        }
        __syncthreads();
        if (tid == 0) { g_T[b] = sT; g_ok[b] = 0; }
    }
}

// ---------------- kernel 3: fused select + sort + gather + per-class NMS + output ----------------
#define OFF_KEY   0                         // u64[4096]          32768
#define OFF_OFFB  32768                     // float4[1024]       16384
#define OFF_SELB  49152                     // float4[1024]       16384
#define OFF_SCORE 65536                     // float[1024]         4096
#define OFF_KEEP  69632                     // int[1024]           4096
#define OFF_CLS   73728                     // ushort[1024]        2048
#define OFF_LIST  75776                     // ushort[1024]        2048
#define OFF_CCNT  77824                     // int[80]              320
#define OFF_COFF  78144                     // int[80]              320
#define OFF_WSUM  78464                     // int[32]              128
#define SMEM_FINAL 78592

__global__ void k_final(const float* __restrict__ x, float* __restrict__ out) {
    extern __shared__ unsigned char sm[];
    u64*            key  = (u64*)(sm + OFF_KEY);
    float4*         offb = (float4*)(sm + OFF_OFFB);
    float4*         selb = (float4*)(sm + OFF_SELB);
    float*          scr  = (float*)(sm + OFF_SCORE);
    int*            keep = (int*)(sm + OFF_KEEP);
    unsigned short* cls  = (unsigned short*)(sm + OFF_CLS);
    unsigned short* list = (unsigned short*)(sm + OFF_LIST);
    int*            ccnt = (int*)(sm + OFF_CCNT);
    int*            coff = (int*)(sm + OFF_COFF);
    int*            wsum = (int*)(sm + OFF_WSUM);
    __shared__ int cnt_s;

    int b = blockIdx.x;
    int tid = threadIdx.x;                  // 0..1023
    int lane = tid & 31, warp = tid >> 5;
    const float* xb = x + (size_t)b * NBOX * NCH;

    // zero output rows for this image (replaces k_zero)
    for (int i = tid; i < MAXDET * 6; i += 1024) out[(size_t)b * MAXDET * 6 + i] = 0.0f;

    for (int i = tid; i < CAP; i += 1024) key[i] = 0ULL;
    if (tid == 0) cnt_s = 0;
    __syncthreads();

    int T = g_T[b];
    if (g_ok[b]) {
        // ---- select from prefilter list with bin >= T ----
        int pn = min(g_precnt[b], PRECAP);
        for (int i0 = 0; i0 < pn; i0 += 1024) {
            int i = i0 + tid;
            bool take = false; u64 kk = 0;
            if (i < pn) {
                kk = g_pre[b][i];
                take = ((int)(kk >> 44) - 0x3E800) >= T;
            }
            unsigned m = __ballot_sync(0xffffffffu, take);
            if (m) {
                int leader = __ffs(m) - 1;
                int basep = 0;
                if (lane == leader) basep = atomicAdd(&cnt_s, __popc(m));
                basep = __shfl_sync(0xffffffffu, basep, leader);
                if (take) {
                    int pos = basep + __popc(m & ((1u << lane) - 1u));
                    if (pos < CAP) key[pos] = kk;
                }
            }
        }
    } else {
        // ---- FALLBACK: full-image compact (warp-per-box, 32 warps) ----
        for (int box = warp; box < NBOX; box += 32) {
            const float* p = xb + (size_t)box * NCH;
            float obj = p[4];
            if (obj <= CONF) continue;
            #pragma unroll
            for (int r = 0; r < 3; r++) {
                int c = r * 32 + lane;
                bool take = false; unsigned bits = 0;
                if (c < NC) {
                    float s = __fmul_rn(p[5 + c], obj);
                    if (s > CONF) {
                        bits = __float_as_uint(s);
                        int bin = min(max((int)(bits >> 12) - 0x3E800, 0), NBINS - 1);
                        take = (bin >= T);
                    }
                }
                unsigned m = __ballot_sync(0xffffffffu, take);
                if (m) {
                    int leader = __ffs(m) - 1;
                    int basep = 0;
                    if (lane == leader) basep = atomicAdd(&cnt_s, __popc(m));
                    basep = __shfl_sync(0xffffffffu, basep, leader);
                    if (take) {
                        int pos = basep + __popc(m & ((1u << lane) - 1u));
                        if (pos < CAP) {
                            unsigned ent = (unsigned)(box * NC + c);
                            key[pos] = ((u64)bits << 32) | (u64)(0xFFFFFFFFu - ent);
                        }
                    }
                }
            }
        }
    }
    __syncthreads();
    int cnt = min(cnt_s, CAP);
    unsigned npow = (cnt <= 1024) ? 1024u : ((cnt <= 2048) ? 2048u : 4096u);

    // ---- bitonic sort descending (key = score_bits:~idx == top_k order) ----
    for (unsigned k = 2; k <= npow; k <<= 1) {
        for (unsigned j = k >> 1; j > 0; j >>= 1) {
            for (unsigned i = tid; i < npow; i += 1024) {
                unsigned ixj = i ^ j;
                if (ixj > i) {
                    u64 a = key[i], c2 = key[ixj];
                    bool descBlock = ((i & k) == 0);
                    if (descBlock ? (a < c2) : (a > c2)) { key[i] = c2; key[ixj] = a; }
                }
            }
            __syncthreads();
        }
    }

    // ---- gather top-1000: boxes, scores, classes ----
    if (tid < TOPK_N) {
        u64 kk = key[tid];
        unsigned bits = (unsigned)(kk >> 32);
        float s, x1, y1, x2, y2, cf; int ci = 0;
        if (bits) {
            unsigned ent = 0xFFFFFFFFu - (unsigned)(kk & 0xFFFFFFFFull);
            int bi = (int)(ent / NC);
            ci = (int)(ent - (unsigned)bi * NC);
            const float* p = xb + (size_t)bi * NCH;
            float cx = p[0], cy = p[1], w = p[2], h = p[3];
            x1 = cx - 0.5f * w;  y1 = cy - 0.5f * h;
            x2 = cx + 0.5f * w;  y2 = cy + 0.5f * h;
            cf = (float)ci;
            s = __uint_as_float(bits);
        } else {
            x1 = y1 = x2 = y2 = 0.f; cf = 0.f; s = 0.f;
        }
        selb[tid] = make_float4(x1, y1, x2, y2);
        scr[tid] = s;
        cls[tid] = (unsigned short)ci;
        float off = cf * MAXWH;
        offb[tid] = make_float4(x1 + off, y1 + off, x2 + off, y2 + off);
    }
    keep[tid] = 0;
    __syncthreads();

    // ---- per-class member lists (stable, ascending rank) ----
    for (int c = warp; c < NC; c += 32) {
        int cc = 0;
        for (int ch = 0; ch < 32; ch++) {
            int t = ch * 32 + lane;
            bool mem = (t < TOPK_N) && (scr[t] > 0.0f) && ((int)cls[t] == c);
            cc += __popc(__ballot_sync(0xffffffffu, mem));
        }
        if (lane == 0) ccnt[c] = cc;
    }
    __syncthreads();
    if (tid == 0) { int a = 0; for (int c = 0; c < NC; c++) { coff[c] = a; a += ccnt[c]; } }
    __syncthreads();
    for (int c = warp; c < NC; c += 32) {
        int p = coff[c];
        for (int ch = 0; ch < 32; ch++) {
            int t = ch * 32 + lane;
            bool mem = (t < TOPK_N) && (scr[t] > 0.0f) && ((int)cls[t] == c);
            unsigned m = __ballot_sync(0xffffffffu, mem);
            if (mem) list[p + __popc(m & ((1u << lane) - 1u))] = (unsigned short)t;
            p += __popc(m);
        }
    }
    __syncthreads();

    // ---- greedy NMS per class (cross-class IoU is exactly 0 due to MAXWH offset) ----
    for (int c = warp; c < NC; c += 32) {
        int m = ccnt[c], base = coff[c];
        unsigned sup = 0;                  // lane l owns slots q with q%32==l, bit q>>5
        for (int p = 0; p < m; p++) {
            unsigned w = __shfl_sync(0xffffffffu, sup, p & 31);
            if ((w >> (p >> 5)) & 1u) continue;     // pivot suppressed (warp-uniform)
            int tp = list[base + p];
            if (lane == 0) keep[tp] = 1;
            float4 a = offb[tp];
            float aarea = __fmul_rn(__fsub_rn(a.z, a.x), __fsub_rn(a.w, a.y));
            for (int q = lane; q < m; q += 32) {
                if (q > p && !((sup >> (q >> 5)) & 1u)) {
                    float4 cb = offb[list[base + q]];
                    float ix1 = fmaxf(a.x, cb.x);
                    float iy1 = fmaxf(a.y, cb.y);
                    float ix2 = fminf(a.z, cb.z);
                    float iy2 = fminf(a.w, cb.w);
                    float iw = fmaxf(__fsub_rn(ix2, ix1), 0.0f);
                    float ih = fmaxf(__fsub_rn(iy2, iy1), 0.0f);
                    float inter = __fmul_rn(iw, ih);
                    float carea = __fmul_rn(__fsub_rn(cb.z, cb.x), __fsub_rn(cb.w, cb.y));
                    float uni = __fsub_rn(__fadd_rn(aarea, carea), inter);
                    float iou = __fdiv_rn(inter, fmaxf(uni, 1e-9f));
                    if (iou > IOU_T) sup |= 1u << (q >> 5);
                }
            }
        }
    }
    __syncthreads();

    // ---- rank kept entries (block scan) + write output ----
    int flag = (tid < TOPK_N) ? keep[tid] : 0;
    int v = flag;
    #pragma unroll
    for (int o = 1; o < 32; o <<= 1) {
        int u = __shfl_up_sync(0xffffffffu, v, o);
        if (lane >= o) v += u;
    }
    if (lane == 31) wsum[warp] = v;
    __syncthreads();
    if (warp == 0) {
        int ws = wsum[lane];
        #pragma unroll
        for (int o = 1; o < 32; o <<= 1) {
            int u = __shfl_up_sync(0xffffffffu, ws, o);
            if (lane >= o) ws += u;
        }
        wsum[lane] = ws;
    }
    __syncthreads();
    int incl = v + (warp ? wsum[warp - 1] : 0);
    int r = incl - flag;
    if (flag && r < MAXDET) {
        float4 bx = selb[tid];
        float* o = out + ((size_t)b * MAXDET + r) * 6;
        o[0] = bx.x; o[1] = bx.y; o[2] = bx.z; o[3] = bx.w;
        o[4] = scr[tid];
        o[5] = (float)cls[tid];
    }

    // reset prefilter counter for the next graph replay (deterministic)
    __syncthreads();
    if (tid == 0) g_precnt[b] = 0;
}

// ---------------- launch ----------------
extern "C" void kernel_launch(void* const* d_in, const int* in_sizes, int n_in,
                              void* d_out, int out_size) {
    (void)in_sizes; (void)n_in; (void)out_size;
    const float* x = (const float*)d_in[0];
    float* out = (float*)d_out;

    cudaFuncSetAttribute(k_final, cudaFuncAttributeMaxDynamicSharedMemorySize, SMEM_FINAL);

    k_pre<<<dim3(132, NIMG), 256>>>(x);
    k_check<<<NIMG, 512>>>(x);
    k_final<<<NIMG, 1024, SMEM_FINAL>>>(x, out);
}